// round 1
// baseline (speedup 1.0000x reference)
#include <cuda_runtime.h>

#define LL   9
#define CC   256
#define KK   3
#define VV   25
#define GG   9
#define TT   128
#define NCC  60
#define CINN 3
#define TP   136          // TT + 8 (causal padding)
#define NN   3200         // TT*VV
#define KC   768          // KK*CC

// ---------------- scratch (device globals; no allocation allowed) -------------
__device__ float g_H[2][CC * NN];     // ping-pong layer activations [c][t*V+v]
__device__ float g_HA[KC * NN];       // adjacency-contracted input [(k*C+cp)][t*V+w]
__device__ float g_Z[CC * NN];        // z / tconv-out scratch
__device__ float g_U[CC * TP * VV];   // relu(LN1(z)) with 8-frame left padding
__device__ float g_S[KK * VV];        // per-layer adjacency row sums (for bg term)

// ---------------- input LN + 1x1 conv (fcn_in) --------------------------------
__global__ void k_input(const float* __restrict__ x, const float* __restrict__ lw,
                        const float* __restrict__ lb, const float* __restrict__ Win,
                        const float* __restrict__ bin) {
    int t = blockIdx.x, tid = threadIdx.x;
    __shared__ float hn[CINN * VV];
    __shared__ float stat[2];
    if (tid < CINN * VV) hn[tid] = x[(tid / VV) * NN + t * VV + (tid % VV)];
    __syncthreads();
    if (tid == 0) {
        float s = 0.f, s2 = 0.f;
        for (int i = 0; i < CINN * VV; i++) { float v = hn[i]; s += v; s2 += v * v; }
        float m = s / (float)(CINN * VV);
        stat[0] = m;
        stat[1] = rsqrtf(s2 / (float)(CINN * VV) - m * m + 1e-5f);
    }
    __syncthreads();
    if (tid < CINN * VV) hn[tid] = (hn[tid] - stat[0]) * stat[1] * lw[tid] + lb[tid];
    __syncthreads();
    float w0 = Win[tid * 3], w1 = Win[tid * 3 + 1], w2 = Win[tid * 3 + 2], b = bin[tid];
    float* Ho = g_H[0];
    #pragma unroll
    for (int v = 0; v < VV; v++)
        Ho[tid * NN + t * VV + v] =
            fmaf(w0, hn[v], fmaf(w1, hn[VV + v], fmaf(w2, hn[2 * VV + v], b)));
}

// ------------- HA = H x (A*imp);  block TT also: S rowsums + U left-pad -------
__global__ void k_ha(int pin, const float* __restrict__ Aadj,
                     const float* __restrict__ impl, const float* __restrict__ ln1bl) {
    int t = blockIdx.x, tid = threadIdx.x;
    if (t == TT) {
        if (tid < KK * VV) {
            int k = tid / VV, w = tid % VV;
            float s = 0.f;
            for (int v = 0; v < VV; v++)
                s += Aadj[(k * VV + v) * VV + w] * impl[(k * VV + v) * VV + w];
            g_S[tid] = s;
        }
        // u for t<0: LN of zero frame = bias; relu it
        for (int i = tid; i < CC * 8 * VV; i += 256) {
            int c = i / (8 * VV), r = i % (8 * VV);
            g_U[c * TP * VV + r] = fmaxf(ln1bl[c * VV + (r % VV)], 0.f);
        }
        return;
    }
    __shared__ float Hs[CC * VV];
    __shared__ float As[KK * VV * VV];
    const float* Hi = g_H[pin];
    for (int i = tid; i < CC * VV; i += 256) {
        int c = i / VV, v = i % VV;
        Hs[i] = Hi[c * NN + t * VV + v];
    }
    for (int i = tid; i < KK * VV * VV; i += 256) As[i] = Aadj[i] * impl[i];
    __syncthreads();
    #pragma unroll
    for (int j = 0; j < 3; j++) {
        int r = j * 256 + tid;
        int k = r >> 8, cp = r & 255;
        const float* hrow = &Hs[cp * VV];
        for (int w = 0; w < VV; w++) {
            float s = 0.f;
            #pragma unroll
            for (int v = 0; v < VV; v++) s = fmaf(hrow[v], As[(k * VV + v) * VV + w], s);
            g_HA[r * NN + t * VV + w] = s;
        }
    }
}

// ------------- z = W2(256x768) @ HA(768x3200) + bg-through-adjacency ----------
__global__ void __launch_bounds__(256) k_zgemm(const float* __restrict__ Wgl,
                                               const float* __restrict__ bgl) {
    __shared__ float As[16][65];
    __shared__ __align__(16) float Bs[16][64];
    int n0 = blockIdx.x * 64, c0 = blockIdx.y * 64;
    int tid = threadIdx.x, tx = tid & 15, ty = tid >> 4;
    float acc[4][4] = {};
    for (int r0 = 0; r0 < KC; r0 += 16) {
        int k = r0 >> 8, cp0 = r0 & 255;
        int idx = tid;
        #pragma unroll
        for (int it = 0; it < 4; it++, idx += 256) {
            int cl = idx >> 4, i = idx & 15;
            As[i][cl] = Wgl[(k * CC + c0 + cl) * CC + cp0 + i];
        }
        idx = tid;
        #pragma unroll
        for (int it = 0; it < 4; it++, idx += 256) {
            int kk = idx >> 6, j = idx & 63;
            Bs[kk][j] = g_HA[(r0 + kk) * NN + n0 + j];
        }
        __syncthreads();
        #pragma unroll
        for (int kk = 0; kk < 16; kk++) {
            float a[4];
            #pragma unroll
            for (int i = 0; i < 4; i++) a[i] = As[kk][ty * 4 + i];
            float4 bv = *reinterpret_cast<const float4*>(&Bs[kk][tx * 4]);
            float bb[4] = {bv.x, bv.y, bv.z, bv.w};
            #pragma unroll
            for (int i = 0; i < 4; i++)
                #pragma unroll
                for (int j = 0; j < 4; j++) acc[i][j] = fmaf(a[i], bb[j], acc[i][j]);
        }
        __syncthreads();
    }
    #pragma unroll
    for (int i = 0; i < 4; i++) {
        int c = c0 + ty * 4 + i;
        float b0 = bgl[c], b1 = bgl[CC + c], b2 = bgl[2 * CC + c];
        #pragma unroll
        for (int j = 0; j < 4; j++) {
            int n = n0 + tx * 4 + j, w = n % VV;
            g_Z[c * NN + n] =
                acc[i][j] + b0 * g_S[w] + b1 * g_S[VV + w] + b2 * g_S[2 * VV + w];
        }
    }
}

// ---------------- per-frame LN over (C,V), ReLU, write padded U ----------------
__global__ void k_ln1(const float* __restrict__ lw, const float* __restrict__ lb) {
    int t = blockIdx.x, c = threadIdx.x;
    float z[VV];
    float s = 0.f, s2 = 0.f;
    #pragma unroll
    for (int w = 0; w < VV; w++) {
        z[w] = g_Z[c * NN + t * VV + w];
        s += z[w]; s2 += z[w] * z[w];
    }
    __shared__ float sh[66];
    int lane = c & 31, wid = c >> 5;
    #pragma unroll
    for (int o = 16; o > 0; o >>= 1) {
        s  += __shfl_down_sync(0xffffffffu, s, o);
        s2 += __shfl_down_sync(0xffffffffu, s2, o);
    }
    if (lane == 0) { sh[wid] = s; sh[32 + wid] = s2; }
    __syncthreads();
    if (c == 0) {
        float ts = 0.f, ts2 = 0.f;
        for (int i = 0; i < 8; i++) { ts += sh[i]; ts2 += sh[32 + i]; }
        float m = ts / 6400.f;
        sh[64] = m;
        sh[65] = rsqrtf(ts2 / 6400.f - m * m + 1e-5f);
    }
    __syncthreads();
    float m = sh[64], r = sh[65];
    #pragma unroll
    for (int w = 0; w < VV; w++) {
        float u = (z[w] - m) * r * lw[c * VV + w] + lb[c * VV + w];
        g_U[c * TP * VV + (t + 8) * VV + w] = fmaxf(u, 0.f);
    }
}

// ------------- causal temporal conv: out[o,t,v] = sum_{c,g} Wt*u --------------
#define TCH 16
__global__ void __launch_bounds__(256) k_tconv(const float* __restrict__ Wtl,
                                               const float* __restrict__ btl) {
    __shared__ __align__(16) float Us[TCH * 16 * 28];  // [c][t_span 16][v pad 28]
    __shared__ float Ws[TCH * 9 * 32];                 // [c][g][o_lane]
    int t0 = blockIdx.x * 8;
    int o0 = blockIdx.y * 32;
    int tid = threadIdx.x;
    int lane = tid & 31;   // o within tile
    int tw = tid >> 5;     // t within tile (warp id)
    float acc[28];
    #pragma unroll
    for (int i = 0; i < 28; i++) acc[i] = 0.f;
    for (int cb = 0; cb < CC; cb += TCH) {
        for (int i = tid; i < TCH * 16 * VV; i += 256) {
            int cl = i / (16 * VV), r = i % (16 * VV);
            Us[(cl * 16 + r / VV) * 28 + (r % VV)] =
                g_U[(cb + cl) * TP * VV + t0 * VV + r];
        }
        for (int i = tid; i < TCH * 16 * 3; i += 256) {
            int cl = i / 48, r = i % 48;
            Us[(cl * 16 + r / 3) * 28 + VV + (r % 3)] = 0.f;
        }
        for (int i = tid; i < 32 * TCH * 9; i += 256) {
            int ol = i / (TCH * 9), r = i % (TCH * 9);
            int cl = r / 9, gg = r % 9;
            Ws[(cl * 9 + gg) * 32 + ol] =
                Wtl[(o0 + ol) * (CC * GG) + (cb + cl) * GG + gg];
        }
        __syncthreads();
        for (int cl = 0; cl < TCH; cl++) {
            #pragma unroll
            for (int gg = 0; gg < GG; gg++) {
                float wv = Ws[(cl * 9 + gg) * 32 + lane];
                const float4* up =
                    reinterpret_cast<const float4*>(&Us[(cl * 16 + tw + 8 - gg) * 28]);
                #pragma unroll
                for (int j = 0; j < 7; j++) {
                    float4 u = up[j];
                    acc[4 * j + 0] = fmaf(wv, u.x, acc[4 * j + 0]);
                    acc[4 * j + 1] = fmaf(wv, u.y, acc[4 * j + 1]);
                    acc[4 * j + 2] = fmaf(wv, u.z, acc[4 * j + 2]);
                    acc[4 * j + 3] = fmaf(wv, u.w, acc[4 * j + 3]);
                }
            }
        }
        __syncthreads();
    }
    int o = o0 + lane, t = t0 + tw;
    float bt = btl[o];
    #pragma unroll
    for (int v = 0; v < VV; v++)
        g_Z[o * NN + t * VV + v] = acc[v] + bt;
}

// ---------------- LN2 + center residual + ReLU --------------------------------
__global__ void k_ln2res(int pin, const float* __restrict__ lw,
                         const float* __restrict__ lb) {
    int t = blockIdx.x, c = threadIdx.x;
    float z[VV];
    float s = 0.f, s2 = 0.f;
    #pragma unroll
    for (int w = 0; w < VV; w++) {
        z[w] = g_Z[c * NN + t * VV + w];
        s += z[w]; s2 += z[w] * z[w];
    }
    __shared__ float sh[66];
    int lane = c & 31, wid = c >> 5;
    #pragma unroll
    for (int o = 16; o > 0; o >>= 1) {
        s  += __shfl_down_sync(0xffffffffu, s, o);
        s2 += __shfl_down_sync(0xffffffffu, s2, o);
    }
    if (lane == 0) { sh[wid] = s; sh[32 + wid] = s2; }
    __syncthreads();
    if (c == 0) {
        float ts = 0.f, ts2 = 0.f;
        for (int i = 0; i < 8; i++) { ts += sh[i]; ts2 += sh[32 + i]; }
        float m = ts / 6400.f;
        sh[64] = m;
        sh[65] = rsqrtf(ts2 / 6400.f - m * m + 1e-5f);
    }
    __syncthreads();
    float m = sh[64], r = sh[65];
    const float* Hi = g_H[pin];
    float* Ho = g_H[pin ^ 1];
    #pragma unroll
    for (int w = 0; w < VV; w++) {
        float val = (z[w] - m) * r * lw[c * VV + w] + lb[c * VV + w];
        float res = (t >= 4) ? Hi[c * NN + (t - 4) * VV + w] : 0.f;
        Ho[c * NN + t * VV + w] = fmaxf(val + res, 0.f);
    }
}

// ---------------- global pool over V + classifier -----------------------------
__global__ void k_out(int pin, const float* __restrict__ Wout,
                      const float* __restrict__ bout, float* __restrict__ out) {
    int t = blockIdx.x, tid = threadIdx.x;
    __shared__ float pooled[CC];
    const float* Hf = g_H[pin];
    float s = 0.f;
    #pragma unroll
    for (int v = 0; v < VV; v++) s += Hf[tid * NN + t * VV + v];
    pooled[tid] = s * (1.f / (float)VV);
    __syncthreads();
    if (tid < NCC) {
        float acc = bout[tid];
        for (int c = 0; c < CC; c++) acc = fmaf(Wout[tid * CC + c], pooled[c], acc);
        out[t * NCC + tid] = acc;
    }
}

// ------------------------------- launcher -------------------------------------
extern "C" void kernel_launch(void* const* d_in, const int* in_sizes, int n_in,
                              void* d_out, int out_size) {
    const float* x    = (const float*)d_in[0];
    const float* Aadj = (const float*)d_in[1];
    const float* lniw = (const float*)d_in[2];
    const float* lnib = (const float*)d_in[3];
    const float* Win  = (const float*)d_in[4];
    const float* bin  = (const float*)d_in[5];
    const float* Wg   = (const float*)d_in[6];
    const float* bg   = (const float*)d_in[7];
    const float* ln1w = (const float*)d_in[8];
    const float* ln1b = (const float*)d_in[9];
    const float* Wt   = (const float*)d_in[10];
    const float* bt   = (const float*)d_in[11];
    const float* ln2w = (const float*)d_in[12];
    const float* ln2b = (const float*)d_in[13];
    const float* imp  = (const float*)d_in[14];
    const float* Wout = (const float*)d_in[15];
    const float* bout = (const float*)d_in[16];
    float* out = (float*)d_out;

    k_input<<<TT, 256>>>(x, lniw, lnib, Win, bin);
    for (int l = 0; l < LL; l++) {
        int pin = l & 1;
        k_ha<<<TT + 1, 256>>>(pin, Aadj, imp + l * KK * VV * VV, ln1b + l * CC * VV);
        k_zgemm<<<dim3(50, 4), 256>>>(Wg + l * KC * CC, bg + l * KC);
        k_ln1<<<TT, 256>>>(ln1w + l * CC * VV, ln1b + l * CC * VV);
        k_tconv<<<dim3(16, 8), 256>>>(Wt + l * CC * CC * GG, bt + l * CC);
        k_ln2res<<<TT, 256>>>(pin, ln2w + l * CC * VV, ln2b + l * CC * VV);
    }
    k_out<<<TT, 256>>>(1, Wout, bout, out);
}

// round 2
// speedup vs baseline: 1.0570x; 1.0570x over previous
#include <cuda_runtime.h>

#define LL   9
#define CC   256
#define KK   3
#define VV   25
#define GG   9
#define TT   128
#define NCC  60
#define CINN 3
#define TP   136          // TT + 8 (causal padding)
#define NN   3200         // TT*VV
#define KC   768          // KK*CC

typedef unsigned long long ull;

__device__ __forceinline__ ull fma2(ull a, ull b, ull c) {
    ull d;
    asm("fma.rn.f32x2 %0, %1, %2, %3;" : "=l"(d) : "l"(a), "l"(b), "l"(c));
    return d;
}
__device__ __forceinline__ ull pack2(float x, float y) {
    ull d;
    asm("mov.b64 %0, {%1, %2};" : "=l"(d) : "f"(x), "f"(y));
    return d;
}
__device__ __forceinline__ float2 unpack2(ull a) {
    float x, y;
    asm("mov.b64 {%0, %1}, %2;" : "=f"(x), "=f"(y) : "l"(a));
    return make_float2(x, y);
}

// ---------------- scratch (device globals; no allocation allowed) -------------
__device__ float g_H[2][CC * NN];     // ping-pong layer activations [c][t*V+v]
__device__ float g_HA[KC * NN];       // adjacency-contracted input [(k*C+cp)][t*V+w]
__device__ float g_Z[CC * NN];        // z / tconv-out scratch
__device__ float g_U[CC * TP * VV];   // relu(LN1(z)) with 8-frame left padding
__device__ float g_S[KK * VV];        // per-layer adjacency row sums (for bg term)

// ---------------- block reduce helper (256 threads) ---------------------------
__device__ __forceinline__ float2 ln_stats(float s, float s2, float* sh, float inv_n) {
    int lane = threadIdx.x & 31, wid = threadIdx.x >> 5;
    #pragma unroll
    for (int o = 16; o > 0; o >>= 1) {
        s  += __shfl_down_sync(0xffffffffu, s, o);
        s2 += __shfl_down_sync(0xffffffffu, s2, o);
    }
    if (lane == 0) { sh[wid] = s; sh[8 + wid] = s2; }
    __syncthreads();
    if (threadIdx.x == 0) {
        float ts = 0.f, ts2 = 0.f;
        #pragma unroll
        for (int i = 0; i < 8; i++) { ts += sh[i]; ts2 += sh[8 + i]; }
        float m = ts * inv_n;
        sh[16] = m;
        sh[17] = rsqrtf(ts2 * inv_n - m * m + 1e-5f);
    }
    __syncthreads();
    return make_float2(sh[16], sh[17]);
}

// ---------------- input LN + 1x1 conv (fcn_in) --------------------------------
__global__ void k_input(const float* __restrict__ x, const float* __restrict__ lw,
                        const float* __restrict__ lb, const float* __restrict__ Win,
                        const float* __restrict__ bin) {
    int t = blockIdx.x, tid = threadIdx.x;
    __shared__ float hn[CINN * VV];
    __shared__ float stat[2];
    if (tid < CINN * VV) hn[tid] = x[(tid / VV) * NN + t * VV + (tid % VV)];
    __syncthreads();
    if (tid == 0) {
        float s = 0.f, s2 = 0.f;
        for (int i = 0; i < CINN * VV; i++) { float v = hn[i]; s += v; s2 += v * v; }
        float m = s / (float)(CINN * VV);
        stat[0] = m;
        stat[1] = rsqrtf(s2 / (float)(CINN * VV) - m * m + 1e-5f);
    }
    __syncthreads();
    if (tid < CINN * VV) hn[tid] = (hn[tid] - stat[0]) * stat[1] * lw[tid] + lb[tid];
    __syncthreads();
    float w0 = Win[tid * 3], w1 = Win[tid * 3 + 1], w2 = Win[tid * 3 + 2], b = bin[tid];
    float* Ho = g_H[0];
    #pragma unroll
    for (int v = 0; v < VV; v++)
        Ho[tid * NN + t * VV + v] =
            fmaf(w0, hn[v], fmaf(w1, hn[VV + v], fmaf(w2, hn[2 * VV + v], b)));
}

// ------------- HA = H x (A*imp);  block TT also: S rowsums + U left-pad -------
__global__ void k_ha(int pin, const float* __restrict__ Aadj,
                     const float* __restrict__ impl, const float* __restrict__ ln1bl) {
    int t = blockIdx.x, tid = threadIdx.x;
    if (t == TT) {
        if (tid < KK * VV) {
            int k = tid / VV, w = tid % VV;
            float s = 0.f;
            for (int v = 0; v < VV; v++)
                s += Aadj[(k * VV + v) * VV + w] * impl[(k * VV + v) * VV + w];
            g_S[tid] = s;
        }
        // u for t<0: LN of zero frame = bias; relu it
        for (int i = tid; i < CC * 8 * VV; i += 256) {
            int c = i / (8 * VV), r = i % (8 * VV);
            g_U[c * TP * VV + r] = fmaxf(ln1bl[c * VV + (r % VV)], 0.f);
        }
        return;
    }
    __shared__ float Hs[CC * VV];
    __shared__ float As[KK * VV * VV];
    const float* Hi = g_H[pin];
    for (int i = tid; i < CC * VV; i += 256) {
        int c = i / VV, v = i % VV;
        Hs[i] = Hi[c * NN + t * VV + v];
    }
    for (int i = tid; i < KK * VV * VV; i += 256) As[i] = Aadj[i] * impl[i];
    __syncthreads();
    #pragma unroll
    for (int j = 0; j < 3; j++) {
        int r = j * 256 + tid;
        int k = r >> 8, cp = r & 255;
        const float* hrow = &Hs[cp * VV];
        for (int w = 0; w < VV; w++) {
            float s = 0.f;
            #pragma unroll
            for (int v = 0; v < VV; v++) s = fmaf(hrow[v], As[(k * VV + v) * VV + w], s);
            g_HA[r * NN + t * VV + w] = s;
        }
    }
}

// ------------- z = W2(256x768) @ HA(768x3200) + bg-through-adjacency ----------
// f32x2: pair over output rows (i). 64x64 tile, 4x4 microtile per thread.
__global__ void __launch_bounds__(256) k_zgemm(const float* __restrict__ Wgl,
                                               const float* __restrict__ bgl) {
    __shared__ __align__(16) float As[16][66];
    __shared__ __align__(16) float Bs[16][64];
    int n0 = blockIdx.x * 64, c0 = blockIdx.y * 64;
    int tid = threadIdx.x, tx = tid & 15, ty = tid >> 4;
    ull acc2[2][4];
    #pragma unroll
    for (int p = 0; p < 2; p++)
        #pragma unroll
        for (int j = 0; j < 4; j++) acc2[p][j] = 0ull;
    for (int r0 = 0; r0 < KC; r0 += 16) {
        int k = r0 >> 8, cp0 = r0 & 255;
        int idx = tid;
        #pragma unroll
        for (int it = 0; it < 4; it++, idx += 256) {
            int cl = idx >> 4, i = idx & 15;
            As[i][cl] = Wgl[(k * CC + c0 + cl) * CC + cp0 + i];
        }
        idx = tid;
        #pragma unroll
        for (int it = 0; it < 4; it++, idx += 256) {
            int kk = idx >> 6, j = idx & 63;
            Bs[kk][j] = g_HA[(r0 + kk) * NN + n0 + j];
        }
        __syncthreads();
        #pragma unroll
        for (int kk = 0; kk < 16; kk++) {
            const ull* arow = reinterpret_cast<const ull*>(&As[kk][0]);
            ull a0 = arow[ty * 2], a1 = arow[ty * 2 + 1];
            float4 bv = *reinterpret_cast<const float4*>(&Bs[kk][tx * 4]);
            ull b0 = pack2(bv.x, bv.x), b1 = pack2(bv.y, bv.y);
            ull b2 = pack2(bv.z, bv.z), b3 = pack2(bv.w, bv.w);
            acc2[0][0] = fma2(a0, b0, acc2[0][0]);
            acc2[0][1] = fma2(a0, b1, acc2[0][1]);
            acc2[0][2] = fma2(a0, b2, acc2[0][2]);
            acc2[0][3] = fma2(a0, b3, acc2[0][3]);
            acc2[1][0] = fma2(a1, b0, acc2[1][0]);
            acc2[1][1] = fma2(a1, b1, acc2[1][1]);
            acc2[1][2] = fma2(a1, b2, acc2[1][2]);
            acc2[1][3] = fma2(a1, b3, acc2[1][3]);
        }
        __syncthreads();
    }
    #pragma unroll
    for (int p = 0; p < 2; p++) {
        int ca = c0 + ty * 4 + 2 * p;
        float b0a = bgl[ca],     b1a = bgl[CC + ca],     b2a = bgl[2 * CC + ca];
        float b0b = bgl[ca + 1], b1b = bgl[CC + ca + 1], b2b = bgl[2 * CC + ca + 1];
        #pragma unroll
        for (int j = 0; j < 4; j++) {
            int n = n0 + tx * 4 + j, w = n % VV;
            float2 v = unpack2(acc2[p][j]);
            float sb0 = g_S[w], sb1 = g_S[VV + w], sb2 = g_S[2 * VV + w];
            g_Z[ca * NN + n]       = v.x + b0a * sb0 + b1a * sb1 + b2a * sb2;
            g_Z[(ca + 1) * NN + n] = v.y + b0b * sb0 + b1b * sb1 + b2b * sb2;
        }
    }
}

// ---------------- per-frame LN over (C,V), ReLU, write padded U ----------------
__global__ void k_ln1(const float* __restrict__ lw, const float* __restrict__ lb) {
    int t = blockIdx.x, tid = threadIdx.x;
    __shared__ float zs[CC * VV];
    __shared__ float sh[18];
    float s = 0.f, s2 = 0.f;
    #pragma unroll
    for (int j = 0; j < VV; j++) {
        int idx = j * 256 + tid;
        int c = idx / VV, w = idx - c * VV;
        float v = g_Z[c * NN + t * VV + w];
        zs[idx] = v;
        s += v; s2 += v * v;
    }
    __syncthreads();
    float2 st = ln_stats(s, s2, sh, 1.f / 6400.f);
    #pragma unroll
    for (int j = 0; j < VV; j++) {
        int idx = j * 256 + tid;
        int c = idx / VV, w = idx - c * VV;
        float u = (zs[idx] - st.x) * st.y * lw[idx] + lb[idx];
        g_U[c * TP * VV + (t + 8) * VV + w] = fmaxf(u, 0.f);
    }
}

// ------------- causal temporal conv: out[o,t,v] = sum_{c,g} Wt*u --------------
// f32x2 paired over channels. Block: 128 threads (lane=o within 32-tile, warp=t
// within 4-tile). Grid: (32 t-blocks, 8 o-blocks) = 256 blocks.
#define TCH 16
__global__ void __launch_bounds__(128) k_tconv(const float* __restrict__ Wtl,
                                               const float* __restrict__ btl) {
    __shared__ __align__(16) ull Us2[TCH / 2][12][26];   // (c-pair)[t-span][v pad 26]
    __shared__ __align__(16) ull Ws2[TCH / 2][GG][32];   // (c-pair)[g][o-lane]
    float* Usf = reinterpret_cast<float*>(Us2);
    float* Wsf = reinterpret_cast<float*>(Ws2);
    int t0 = blockIdx.x * 4;
    int o0 = blockIdx.y * 32;
    int tid = threadIdx.x;
    int lane = tid & 31;   // o within tile
    int tw = tid >> 5;     // t within tile
    ull acc2[26];
    #pragma unroll
    for (int i = 0; i < 26; i++) acc2[i] = 0ull;
    for (int cb = 0; cb < CC; cb += TCH) {
        // fill Us2: channels cb..cb+15 interleaved in pairs
        for (int i = tid; i < TCH * 12 * VV; i += 128) {
            int cl = i / (12 * VV), r = i - cl * (12 * VV);
            int trow = r / VV, v = r - trow * VV;
            int c2 = cl >> 1, par = cl & 1;
            Usf[(((c2 * 12 + trow) * 26) + v) * 2 + par] =
                g_U[(cb + cl) * TP * VV + t0 * VV + r];
        }
        // zero pad v=25
        for (int i = tid; i < (TCH / 2) * 12; i += 128) {
            int c2 = i / 12, trow = i - c2 * 12;
            Us2[c2][trow][25] = 0ull;
        }
        // fill Ws2 pairs
        for (int i = tid; i < 32 * TCH * GG; i += 128) {
            int ol = i / (TCH * GG), r = i - ol * (TCH * GG);
            int cl = r / GG, g = r - cl * GG;
            int c2 = cl >> 1, par = cl & 1;
            Wsf[(((c2 * GG + g) * 32) + ol) * 2 + par] =
                Wtl[(o0 + ol) * (CC * GG) + (cb + cl) * GG + g];
        }
        __syncthreads();
        #pragma unroll 2
        for (int c2 = 0; c2 < TCH / 2; c2++) {
            #pragma unroll
            for (int g = 0; g < GG; g++) {
                ull w2 = Ws2[c2][g][lane];
                const ulonglong2* up =
                    reinterpret_cast<const ulonglong2*>(&Us2[c2][tw + 8 - g][0]);
                #pragma unroll
                for (int j = 0; j < 13; j++) {
                    ulonglong2 u = up[j];
                    acc2[2 * j]     = fma2(w2, u.x, acc2[2 * j]);
                    acc2[2 * j + 1] = fma2(w2, u.y, acc2[2 * j + 1]);
                }
            }
        }
        __syncthreads();
    }
    int o = o0 + lane, t = t0 + tw;
    float bt = btl[o];
    #pragma unroll
    for (int v = 0; v < VV; v++) {
        float2 p = unpack2(acc2[v]);
        g_Z[o * NN + t * VV + v] = p.x + p.y + bt;
    }
}

// ---------------- LN2 + center residual + ReLU --------------------------------
__global__ void k_ln2res(int pin, const float* __restrict__ lw,
                         const float* __restrict__ lb) {
    int t = blockIdx.x, tid = threadIdx.x;
    __shared__ float zs[CC * VV];
    __shared__ float sh[18];
    float s = 0.f, s2 = 0.f;
    #pragma unroll
    for (int j = 0; j < VV; j++) {
        int idx = j * 256 + tid;
        int c = idx / VV, w = idx - c * VV;
        float v = g_Z[c * NN + t * VV + w];
        zs[idx] = v;
        s += v; s2 += v * v;
    }
    __syncthreads();
    float2 st = ln_stats(s, s2, sh, 1.f / 6400.f);
    const float* Hi = g_H[pin];
    float* Ho = g_H[pin ^ 1];
    #pragma unroll
    for (int j = 0; j < VV; j++) {
        int idx = j * 256 + tid;
        int c = idx / VV, w = idx - c * VV;
        float val = (zs[idx] - st.x) * st.y * lw[idx] + lb[idx];
        float res = (t >= 4) ? Hi[c * NN + (t - 4) * VV + w] : 0.f;
        Ho[c * NN + t * VV + w] = fmaxf(val + res, 0.f);
    }
}

// ---------------- global pool over V + classifier -----------------------------
__global__ void k_out(int pin, const float* __restrict__ Wout,
                      const float* __restrict__ bout, float* __restrict__ out) {
    int t = blockIdx.x, tid = threadIdx.x;
    __shared__ float pooled[CC];
    const float* Hf = g_H[pin];
    float s = 0.f;
    #pragma unroll
    for (int v = 0; v < VV; v++) s += Hf[tid * NN + t * VV + v];
    pooled[tid] = s * (1.f / (float)VV);
    __syncthreads();
    if (tid < NCC) {
        float acc = bout[tid];
        for (int c = 0; c < CC; c++) acc = fmaf(Wout[tid * CC + c], pooled[c], acc);
        out[t * NCC + tid] = acc;
    }
}

// ------------------------------- launcher -------------------------------------
extern "C" void kernel_launch(void* const* d_in, const int* in_sizes, int n_in,
                              void* d_out, int out_size) {
    const float* x    = (const float*)d_in[0];
    const float* Aadj = (const float*)d_in[1];
    const float* lniw = (const float*)d_in[2];
    const float* lnib = (const float*)d_in[3];
    const float* Win  = (const float*)d_in[4];
    const float* bin  = (const float*)d_in[5];
    const float* Wg   = (const float*)d_in[6];
    const float* bg   = (const float*)d_in[7];
    const float* ln1w = (const float*)d_in[8];
    const float* ln1b = (const float*)d_in[9];
    const float* Wt   = (const float*)d_in[10];
    const float* bt   = (const float*)d_in[11];
    const float* ln2w = (const float*)d_in[12];
    const float* ln2b = (const float*)d_in[13];
    const float* imp  = (const float*)d_in[14];
    const float* Wout = (const float*)d_in[15];
    const float* bout = (const float*)d_in[16];
    float* out = (float*)d_out;

    k_input<<<TT, 256>>>(x, lniw, lnib, Win, bin);
    for (int l = 0; l < LL; l++) {
        int pin = l & 1;
        k_ha<<<TT + 1, 256>>>(pin, Aadj, imp + l * KK * VV * VV, ln1b + l * CC * VV);
        k_zgemm<<<dim3(50, 4), 256>>>(Wg + l * KC * CC, bg + l * KC);
        k_ln1<<<TT, 256>>>(ln1w + l * CC * VV, ln1b + l * CC * VV);
        k_tconv<<<dim3(32, 8), 128>>>(Wt + l * CC * CC * GG, bt + l * CC);
        k_ln2res<<<TT, 256>>>(pin, ln2w + l * CC * VV, ln2b + l * CC * VV);
    }
    k_out<<<TT, 256>>>(1, Wout, bout, out);
}

// round 3
// speedup vs baseline: 1.5600x; 1.4759x over previous
#include <cuda_runtime.h>

#define LL   9
#define CC   256
#define KK   3
#define VV   25
#define GG   9
#define TT   128
#define NCC  60
#define CINN 3
#define TP   136          // TT + 8 (causal padding)
#define NN   3200         // TT*VV
#define FRA  6400         // CC*VV per frame
#define NPART 16          // tconv channel splits

typedef unsigned long long ull;

__device__ __forceinline__ ull fma2(ull a, ull b, ull c) {
    ull d;
    asm("fma.rn.f32x2 %0, %1, %2, %3;" : "=l"(d) : "l"(a), "l"(b), "l"(c));
    return d;
}
__device__ __forceinline__ ull pack2(float x, float y) {
    ull d;
    asm("mov.b64 %0, {%1, %2};" : "=l"(d) : "f"(x), "f"(y));
    return d;
}
__device__ __forceinline__ float2 unpack2(ull a) {
    float x, y;
    asm("mov.b64 {%0, %1}, %2;" : "=f"(x), "=f"(y) : "l"(a));
    return make_float2(x, y);
}

// ---------------- scratch (device globals) ------------------------------------
__device__ float g_H[2][TT * FRA];            // t-major activations [t][c][v]
__device__ float g_U[CC * TP * VV];           // relu(LN1(z)), [c][tp][v]
__device__ float g_P[NPART][TT * CC * 32];    // tconv partials [p][t][o][32pad]

// ---------------- block reduce helper (256 threads) ---------------------------
__device__ __forceinline__ float2 ln_stats(float s, float s2, float* sh, float inv_n) {
    int lane = threadIdx.x & 31, wid = threadIdx.x >> 5;
    #pragma unroll
    for (int o = 16; o > 0; o >>= 1) {
        s  += __shfl_down_sync(0xffffffffu, s, o);
        s2 += __shfl_down_sync(0xffffffffu, s2, o);
    }
    if (lane == 0) { sh[wid] = s; sh[8 + wid] = s2; }
    __syncthreads();
    if (threadIdx.x == 0) {
        float ts = 0.f, ts2 = 0.f;
        #pragma unroll
        for (int i = 0; i < 8; i++) { ts += sh[i]; ts2 += sh[8 + i]; }
        float m = ts * inv_n;
        sh[16] = m;
        sh[17] = rsqrtf(ts2 * inv_n - m * m + 1e-5f);
    }
    __syncthreads();
    return make_float2(sh[16], sh[17]);
}

// ---------------- input LN + 1x1 conv (fcn_in) --------------------------------
__global__ void k_input(const float* __restrict__ x, const float* __restrict__ lw,
                        const float* __restrict__ lb, const float* __restrict__ Win,
                        const float* __restrict__ bin) {
    int t = blockIdx.x, tid = threadIdx.x;
    __shared__ float hn[CINN * VV];
    __shared__ float stat[2];
    if (tid < CINN * VV) hn[tid] = x[(tid / VV) * NN + t * VV + (tid % VV)];
    __syncthreads();
    if (tid == 0) {
        float s = 0.f, s2 = 0.f;
        for (int i = 0; i < CINN * VV; i++) { float v = hn[i]; s += v; s2 += v * v; }
        float m = s / (float)(CINN * VV);
        stat[0] = m;
        stat[1] = rsqrtf(s2 / (float)(CINN * VV) - m * m + 1e-5f);
    }
    __syncthreads();
    if (tid < CINN * VV) hn[tid] = (hn[tid] - stat[0]) * stat[1] * lw[tid] + lb[tid];
    __syncthreads();
    float w0 = Win[tid * 3], w1 = Win[tid * 3 + 1], w2 = Win[tid * 3 + 2], b = bin[tid];
    float* Ho = g_H[0];
    #pragma unroll
    for (int v = 0; v < VV; v++)
        Ho[t * FRA + tid * VV + v] =
            fmaf(w0, hn[v], fmaf(w1, hn[VV + v], fmaf(w2, hn[2 * VV + v], b)));
}

// ------ fused per-frame: graph conv (Wg@H then xA) + bias-via-rowsums + LN1 ---
// Block = one timestep t (blocks 0..127); block 128 writes the causal U padding.
__global__ void __launch_bounds__(256) k_gcn(
    int pin, const float* __restrict__ Wgl, const float* __restrict__ bgl,
    const float* __restrict__ Aadj, const float* __restrict__ impl,
    const float* __restrict__ lw, const float* __restrict__ lb) {
    int tid = threadIdx.x;
    if (blockIdx.x == TT) {
        // u for t<0: relu(LN(zero frame)) = relu(ln1_b)
        for (int i = tid; i < CC * 8 * VV; i += 256) {
            int c = i / (8 * VV), r = i % (8 * VV);
            g_U[c * TP * VV + r] = fmaxf(lb[c * VV + (r % VV)], 0.f);
        }
        return;
    }
    int t = blockIdx.x;
    __shared__ __align__(16) float Hs[CC * 28];       // [cp][v pad28]
    __shared__ __align__(16) float As[KK * VV * 28];  // [k][v][w pad28]
    __shared__ float Ss[KK * VV];                     // adjacency col sums
    __shared__ float red[18];
    const float* Hp = g_H[pin];

    for (int i = tid; i < CC * 28; i += 256) {
        int cp = i / 28, v = i - cp * 28;
        Hs[i] = (v < VV) ? Hp[t * FRA + cp * VV + v] : 0.f;
    }
    for (int i = tid; i < KK * VV * 28; i += 256) {
        int kv = i / 28, w = i - kv * 28;
        As[i] = (w < VV) ? Aadj[kv * VV + w] * impl[kv * VV + w] : 0.f;
    }
    __syncthreads();
    if (tid < KK * VV) {
        int k = tid / VV, w = tid - k * VV;
        float s = 0.f;
        #pragma unroll
        for (int v = 0; v < VV; v++) s += As[(k * VV + v) * 28 + w];
        Ss[tid] = s;
    }

    // ---- Y[k][v] = sum_cp Wg[k*C+c, cp] * H[cp, v]  (f32x2 over v-pairs) ----
    int c = tid;
    const float4* wr0 = reinterpret_cast<const float4*>(Wgl + (size_t)(0 * CC + c) * CC);
    const float4* wr1 = reinterpret_cast<const float4*>(Wgl + (size_t)(1 * CC + c) * CC);
    const float4* wr2 = reinterpret_cast<const float4*>(Wgl + (size_t)(2 * CC + c) * CC);
    ull Y0[13], Y1[13], Y2[13];
    #pragma unroll
    for (int j = 0; j < 13; j++) { Y0[j] = 0ull; Y1[j] = 0ull; Y2[j] = 0ull; }
    for (int q = 0; q < CC / 4; q++) {
        float4 w0 = wr0[q], w1 = wr1[q], w2 = wr2[q];
        const float* w0p = &w0.x;
        const float* w1p = &w1.x;
        const float* w2p = &w2.x;
        #pragma unroll
        for (int u = 0; u < 4; u++) {
            ull p0 = pack2(w0p[u], w0p[u]);
            ull p1 = pack2(w1p[u], w1p[u]);
            ull p2 = pack2(w2p[u], w2p[u]);
            const ull* hr = reinterpret_cast<const ull*>(&Hs[(q * 4 + u) * 28]);
            #pragma unroll
            for (int j = 0; j < 13; j++) {
                ull h = hr[j];
                Y0[j] = fma2(p0, h, Y0[j]);
                Y1[j] = fma2(p1, h, Y1[j]);
                Y2[j] = fma2(p2, h, Y2[j]);
            }
        }
    }
    float y[KK][VV + 1];
    #pragma unroll
    for (int j = 0; j < 13; j++) {
        float2 a = unpack2(Y0[j]); y[0][2 * j] = a.x; y[0][2 * j + 1] = a.y;
        float2 b = unpack2(Y1[j]); y[1][2 * j] = b.x; y[1][2 * j + 1] = b.y;
        float2 d = unpack2(Y2[j]); y[2][2 * j] = d.x; y[2][2 * j + 1] = d.y;
    }
    __syncthreads();   // Ss ready

    // ---- z[w] = sum_k sum_v y[k][v] * As[k][v][w]  (f32x2 over w-pairs) ------
    ull zacc[14];
    #pragma unroll
    for (int j = 0; j < 14; j++) zacc[j] = 0ull;
    #pragma unroll
    for (int k = 0; k < KK; k++) {
        for (int v = 0; v < VV; v++) {
            ull yy = pack2(y[k][v], y[k][v]);
            const ull* ar = reinterpret_cast<const ull*>(&As[(k * VV + v) * 28]);
            #pragma unroll
            for (int j = 0; j < 14; j++) zacc[j] = fma2(yy, ar[j], zacc[j]);
        }
    }
    float z[VV + 3];
    #pragma unroll
    for (int j = 0; j < 14; j++) {
        float2 a = unpack2(zacc[j]);
        z[2 * j] = a.x;
        if (2 * j + 1 < VV + 3) z[2 * j + 1] = a.y;
    }
    float b0 = bgl[c], b1 = bgl[CC + c], b2 = bgl[2 * CC + c];
    float s = 0.f, s2 = 0.f;
    #pragma unroll
    for (int w = 0; w < VV; w++) {
        z[w] += b0 * Ss[w] + b1 * Ss[VV + w] + b2 * Ss[2 * VV + w];
        s += z[w]; s2 += z[w] * z[w];
    }
    float2 st = ln_stats(s, s2, red, 1.f / (float)FRA);
    #pragma unroll
    for (int w = 0; w < VV; w++) {
        float u = (z[w] - st.x) * st.y * lw[c * VV + w] + lb[c * VV + w];
        g_U[c * TP * VV + (t + 8) * VV + w] = fmaxf(u, 0.f);
    }
}

// ------------- causal temporal conv, 16-way channel split -> partials ---------
// grid (32 t-blocks x 4 o-blocks x 16 c-splits), 128 threads.
// lane = o-in-tile (x2: lane and lane+32), warp = t-in-tile (4).
__global__ void __launch_bounds__(128) k_tconv(const float* __restrict__ Wtl) {
    __shared__ __align__(16) ull Us2[8][12][26];   // c-pairs x t-span x v(pad26)
    __shared__ __align__(16) ull Ws2[8][GG][64];   // c-pairs x g x o
    float* Usf = reinterpret_cast<float*>(Us2);
    float* Wsf = reinterpret_cast<float*>(Ws2);
    int t0 = blockIdx.x * 4;
    int o0 = blockIdx.y * 64;
    int cb = blockIdx.z * 16;
    int tid = threadIdx.x;
    int lane = tid & 31, tw = tid >> 5;

    for (int i = tid; i < 16 * 12 * VV; i += 128) {
        int cl = i / (12 * VV), r = i - cl * (12 * VV);
        int trow = r / VV, v = r - trow * VV;
        Usf[((((cl >> 1) * 12 + trow) * 26) + v) * 2 + (cl & 1)] =
            g_U[(cb + cl) * TP * VV + t0 * VV + r];
    }
    for (int i = tid; i < 8 * 12; i += 128) Us2[i / 12][i % 12][25] = 0ull;
    for (int i = tid; i < 64 * 16 * GG; i += 128) {
        int ol = i / (16 * GG), r = i - ol * (16 * GG);
        int cl = r / GG, g = r - cl * GG;
        Wsf[((((cl >> 1) * GG + g) * 64) + ol) * 2 + (cl & 1)] =
            Wtl[(o0 + ol) * (CC * GG) + (cb + cl) * GG + g];
    }
    __syncthreads();

    ull accA[26], accB[26];
    #pragma unroll
    for (int i = 0; i < 26; i++) { accA[i] = 0ull; accB[i] = 0ull; }
    #pragma unroll 2
    for (int c2 = 0; c2 < 8; c2++) {
        #pragma unroll
        for (int g = 0; g < GG; g++) {
            ull wa = Ws2[c2][g][lane];
            ull wb = Ws2[c2][g][lane + 32];
            const ulonglong2* up =
                reinterpret_cast<const ulonglong2*>(&Us2[c2][tw + 8 - g][0]);
            #pragma unroll
            for (int j = 0; j < 13; j++) {
                ulonglong2 u = up[j];
                accA[2 * j]     = fma2(wa, u.x, accA[2 * j]);
                accA[2 * j + 1] = fma2(wa, u.y, accA[2 * j + 1]);
                accB[2 * j]     = fma2(wb, u.x, accB[2 * j]);
                accB[2 * j + 1] = fma2(wb, u.y, accB[2 * j + 1]);
            }
        }
    }
    int t = t0 + tw;
    float* dstA = &g_P[blockIdx.z][(t * CC + o0 + lane) * 32];
    float* dstB = &g_P[blockIdx.z][(t * CC + o0 + lane + 32) * 32];
    float va[VV + 1], vb[VV + 1];
    #pragma unroll
    for (int v = 0; v < 26; v++) {
        float2 a = unpack2(accA[v]); va[v] = a.x + a.y;
        float2 b = unpack2(accB[v]); vb[v] = b.x + b.y;
    }
    #pragma unroll
    for (int j = 0; j < 6; j++) {
        reinterpret_cast<float4*>(dstA)[j] =
            make_float4(va[4 * j], va[4 * j + 1], va[4 * j + 2], va[4 * j + 3]);
        reinterpret_cast<float4*>(dstB)[j] =
            make_float4(vb[4 * j], vb[4 * j + 1], vb[4 * j + 2], vb[4 * j + 3]);
    }
    dstA[24] = va[24];
    dstB[24] = vb[24];
}

// -------- reduce partials + tconv bias + LN2 + center residual + ReLU ---------
__global__ void __launch_bounds__(256) k_ln2res(
    int pin, const float* __restrict__ btl,
    const float* __restrict__ lw, const float* __restrict__ lb) {
    int t = blockIdx.x, c = threadIdx.x;
    __shared__ float red[18];
    float z[VV];
    float bt = btl[c];
    #pragma unroll
    for (int w = 0; w < VV; w++) z[w] = bt;
    for (int p = 0; p < NPART; p++) {
        const float* src = &g_P[p][(t * CC + c) * 32];
        #pragma unroll
        for (int j = 0; j < 6; j++) {
            float4 f = reinterpret_cast<const float4*>(src)[j];
            z[4 * j] += f.x; z[4 * j + 1] += f.y;
            z[4 * j + 2] += f.z; z[4 * j + 3] += f.w;
        }
        z[24] += src[24];
    }
    float s = 0.f, s2 = 0.f;
    #pragma unroll
    for (int w = 0; w < VV; w++) { s += z[w]; s2 += z[w] * z[w]; }
    float2 st = ln_stats(s, s2, red, 1.f / (float)FRA);
    const float* Hi = g_H[pin];
    float* Ho = g_H[pin ^ 1];
    #pragma unroll
    for (int w = 0; w < VV; w++) {
        float val = (z[w] - st.x) * st.y * lw[c * VV + w] + lb[c * VV + w];
        float res = (t >= 4) ? Hi[(t - 4) * FRA + c * VV + w] : 0.f;
        Ho[t * FRA + c * VV + w] = fmaxf(val + res, 0.f);
    }
}

// ---------------- global pool over V + classifier -----------------------------
__global__ void k_out(const float* __restrict__ Wout,
                      const float* __restrict__ bout, float* __restrict__ out) {
    int t = blockIdx.x, tid = threadIdx.x;
    __shared__ float pooled[CC];
    const float* Hf = g_H[1];
    float s = 0.f;
    #pragma unroll
    for (int v = 0; v < VV; v++) s += Hf[t * FRA + tid * VV + v];
    pooled[tid] = s * (1.f / (float)VV);
    __syncthreads();
    if (tid < NCC) {
        float acc = bout[tid];
        for (int c = 0; c < CC; c++) acc = fmaf(Wout[tid * CC + c], pooled[c], acc);
        out[t * NCC + tid] = acc;
    }
}

// ------------------------------- launcher -------------------------------------
extern "C" void kernel_launch(void* const* d_in, const int* in_sizes, int n_in,
                              void* d_out, int out_size) {
    const float* x    = (const float*)d_in[0];
    const float* Aadj = (const float*)d_in[1];
    const float* lniw = (const float*)d_in[2];
    const float* lnib = (const float*)d_in[3];
    const float* Win  = (const float*)d_in[4];
    const float* bin  = (const float*)d_in[5];
    const float* Wg   = (const float*)d_in[6];
    const float* bg   = (const float*)d_in[7];
    const float* ln1w = (const float*)d_in[8];
    const float* ln1b = (const float*)d_in[9];
    const float* Wt   = (const float*)d_in[10];
    const float* bt   = (const float*)d_in[11];
    const float* ln2w = (const float*)d_in[12];
    const float* ln2b = (const float*)d_in[13];
    const float* imp  = (const float*)d_in[14];
    const float* Wout = (const float*)d_in[15];
    const float* bout = (const float*)d_in[16];
    float* out = (float*)d_out;

    k_input<<<TT, 256>>>(x, lniw, lnib, Win, bin);
    for (int l = 0; l < LL; l++) {
        int pin = l & 1;
        k_gcn<<<TT + 1, 256>>>(pin, Wg + (size_t)l * KK * CC * CC, bg + l * KK * CC,
                               Aadj, imp + l * KK * VV * VV,
                               ln1w + l * CC * VV, ln1b + l * CC * VV);
        k_tconv<<<dim3(32, 4, 16), 128>>>(Wt + (size_t)l * CC * CC * GG);
        k_ln2res<<<TT, 256>>>(pin, bt + l * CC, ln2w + l * CC * VV, ln2b + l * CC * VV);
    }
    k_out<<<TT, 256>>>(Wout, bout, out);
}

// round 4
// speedup vs baseline: 1.7085x; 1.0952x over previous
#include <cuda_runtime.h>

#define LL   9
#define CC   256
#define KK   3
#define VV   25
#define GG   9
#define TT   128
#define NCC  60
#define CINN 3
#define TP   136          // TT + 8 (causal padding)
#define NN   3200         // TT*VV
#define FRA  6400         // CC*VV per frame
#define KC   768          // KK*CC
#define NPART 4           // tconv channel splits
#define PSTR 28           // partial row stride (floats)

typedef unsigned long long ull;

__device__ __forceinline__ ull fma2(ull a, ull b, ull c) {
    ull d;
    asm("fma.rn.f32x2 %0, %1, %2, %3;" : "=l"(d) : "l"(a), "l"(b), "l"(c));
    return d;
}
__device__ __forceinline__ ull pack2(float x, float y) {
    ull d;
    asm("mov.b64 %0, {%1, %2};" : "=l"(d) : "f"(x), "f"(y));
    return d;
}
__device__ __forceinline__ float2 unpack2(ull a) {
    float x, y;
    asm("mov.b64 {%0, %1}, %2;" : "=f"(x), "=f"(y) : "l"(a));
    return make_float2(x, y);
}

// ---------------- scratch (device globals) ------------------------------------
__device__ float g_H[2][TT * FRA];              // t-major activations [t][c][v]
__device__ float g_U[CC * TP * VV];             // relu(LN1(z)), [c][tp][v]
__device__ float g_P[NPART][TT * CC * PSTR];    // tconv partials
__device__ float g_WgT[LL][CC * KC];            // transposed graph weights [l][cp][k*C+c]

// ---------------- block reduce helper (256 threads) ---------------------------
__device__ __forceinline__ float2 ln_stats(float s, float s2, float* sh, float inv_n) {
    int lane = threadIdx.x & 31, wid = threadIdx.x >> 5;
    #pragma unroll
    for (int o = 16; o > 0; o >>= 1) {
        s  += __shfl_down_sync(0xffffffffu, s, o);
        s2 += __shfl_down_sync(0xffffffffu, s2, o);
    }
    if (lane == 0) { sh[wid] = s; sh[8 + wid] = s2; }
    __syncthreads();
    if (threadIdx.x == 0) {
        float ts = 0.f, ts2 = 0.f;
        #pragma unroll
        for (int i = 0; i < 8; i++) { ts += sh[i]; ts2 += sh[8 + i]; }
        float m = ts * inv_n;
        sh[16] = m;
        sh[17] = rsqrtf(ts2 * inv_n - m * m + 1e-5f);
    }
    __syncthreads();
    return make_float2(sh[16], sh[17]);
}

// ---------------- Wg transpose: [l][r][cp] -> [l][cp][r] ----------------------
__global__ void k_wgt(const float* __restrict__ Wg) {
    __shared__ float tile[32][33];
    int l = blockIdx.z;
    int r0 = blockIdx.x * 32, cp0 = blockIdx.y * 32;
    int tx = threadIdx.x, ty = threadIdx.y;
    #pragma unroll
    for (int j = 0; j < 32; j += 8)
        tile[ty + j][tx] = Wg[((size_t)l * KC + r0 + ty + j) * CC + cp0 + tx];
    __syncthreads();
    #pragma unroll
    for (int j = 0; j < 32; j += 8)
        g_WgT[l][(cp0 + ty + j) * KC + r0 + tx] = tile[tx][ty + j];
}

// ---------------- input LN + 1x1 conv (fcn_in) --------------------------------
__global__ void k_input(const float* __restrict__ x, const float* __restrict__ lw,
                        const float* __restrict__ lb, const float* __restrict__ Win,
                        const float* __restrict__ bin) {
    int t = blockIdx.x, tid = threadIdx.x;
    __shared__ float hn[CINN * VV];
    __shared__ float stat[2];
    if (tid < CINN * VV) hn[tid] = x[(tid / VV) * NN + t * VV + (tid % VV)];
    __syncthreads();
    if (tid == 0) {
        float s = 0.f, s2 = 0.f;
        for (int i = 0; i < CINN * VV; i++) { float v = hn[i]; s += v; s2 += v * v; }
        float m = s / (float)(CINN * VV);
        stat[0] = m;
        stat[1] = rsqrtf(s2 / (float)(CINN * VV) - m * m + 1e-5f);
    }
    __syncthreads();
    if (tid < CINN * VV) hn[tid] = (hn[tid] - stat[0]) * stat[1] * lw[tid] + lb[tid];
    __syncthreads();
    float w0 = Win[tid * 3], w1 = Win[tid * 3 + 1], w2 = Win[tid * 3 + 2], b = bin[tid];
    float* Ho = g_H[0];
    #pragma unroll
    for (int v = 0; v < VV; v++)
        Ho[t * FRA + tid * VV + v] =
            fmaf(w0, hn[v], fmaf(w1, hn[VV + v], fmaf(w2, hn[2 * VV + v], b)));
}

// ---- fused: [LN2res of prev layer] + graph conv + bias-via-rowsums + LN1 -----
// Block = one timestep; block TT writes causal U padding.
__global__ void __launch_bounds__(256) k_gcn(
    int l, const float* __restrict__ bgl,
    const float* __restrict__ Aadj, const float* __restrict__ impl,
    const float* __restrict__ lw1, const float* __restrict__ lb1,
    const float* __restrict__ btp, const float* __restrict__ lw2,
    const float* __restrict__ lb2) {
    int tid = threadIdx.x;
    if (blockIdx.x == TT) {
        for (int i = tid; i < CC * 8 * VV; i += 256) {
            int c = i / (8 * VV), r = i % (8 * VV);
            g_U[c * TP * VV + r] = fmaxf(lb1[c * VV + (r % VV)], 0.f);
        }
        return;
    }
    int t = blockIdx.x;
    __shared__ __align__(16) float Hs[CC * 28];       // [cp][v pad28]
    __shared__ __align__(16) float As[KK * VV * 28];  // [k][v][w pad28]
    __shared__ float Ss[KK * VV];
    __shared__ float red[18];
    int c = tid;

    for (int i = tid; i < KK * VV * 28; i += 256) {
        int kv = i / 28, w = i - kv * 28;
        As[i] = (w < VV) ? Aadj[kv * VV + w] * impl[kv * VV + w] : 0.f;
    }

    if (l == 0) {
        const float* Hp = g_H[0];
        for (int i = tid; i < CC * 28; i += 256) {
            int cp = i / 28, v = i - cp * 28;
            Hs[i] = (v < VV) ? Hp[t * FRA + cp * VV + v] : 0.f;
        }
    } else {
        // ---- reduce tconv partials -> z; LN2; residual; ReLU; -> Hs + g_H ----
        float z[VV + 3];
        float btv = btp[c];
        #pragma unroll
        for (int w = 0; w < VV; w++) z[w] = btv;
        #pragma unroll
        for (int p = 0; p < NPART; p++) {
            const float* src = &g_P[p][(t * CC + c) * PSTR];
            #pragma unroll
            for (int j = 0; j < 6; j++) {
                float4 f = reinterpret_cast<const float4*>(src)[j];
                z[4 * j] += f.x; z[4 * j + 1] += f.y;
                z[4 * j + 2] += f.z; z[4 * j + 3] += f.w;
            }
            z[24] += src[24];
        }
        float s = 0.f, s2 = 0.f;
        #pragma unroll
        for (int w = 0; w < VV; w++) { s += z[w]; s2 += z[w] * z[w]; }
        float2 st = ln_stats(s, s2, red, 1.f / (float)FRA);
        const float* Hi = g_H[(l - 1) & 1];
        float* Ho = g_H[l & 1];
        #pragma unroll
        for (int w = 0; w < VV; w++) {
            float val = (z[w] - st.x) * st.y * lw2[c * VV + w] + lb2[c * VV + w];
            float res = (t >= 4) ? Hi[(t - 4) * FRA + c * VV + w] : 0.f;
            float h = fmaxf(val + res, 0.f);
            Ho[t * FRA + c * VV + w] = h;
            Hs[c * 28 + w] = h;
        }
        Hs[c * 28 + 25] = 0.f;
        Hs[c * 28 + 26] = 0.f;
        Hs[c * 28 + 27] = 0.f;
    }
    __syncthreads();
    if (tid < KK * VV) {
        int k = tid / VV, w = tid - k * VV;
        float s = 0.f;
        #pragma unroll
        for (int v = 0; v < VV; v++) s += As[(k * VV + v) * 28 + w];
        Ss[tid] = s;
    }

    // ---- Y[k][v] = sum_cp WgT[cp][k*C+c] * H[cp][v]  (f32x2 over v-pairs) ----
    const float* WT = g_WgT[l];
    ull Y0[13], Y1[13], Y2[13];
    #pragma unroll
    for (int j = 0; j < 13; j++) { Y0[j] = 0ull; Y1[j] = 0ull; Y2[j] = 0ull; }
    #pragma unroll 4
    for (int cp = 0; cp < CC; cp++) {
        const float* wp = WT + cp * KC;
        float w0 = wp[c], w1 = wp[CC + c], w2 = wp[2 * CC + c];
        ull p0 = pack2(w0, w0), p1 = pack2(w1, w1), p2 = pack2(w2, w2);
        const ull* hr = reinterpret_cast<const ull*>(&Hs[cp * 28]);
        #pragma unroll
        for (int j = 0; j < 13; j++) {
            ull h = hr[j];
            Y0[j] = fma2(p0, h, Y0[j]);
            Y1[j] = fma2(p1, h, Y1[j]);
            Y2[j] = fma2(p2, h, Y2[j]);
        }
    }
    float y[KK][VV + 1];
    #pragma unroll
    for (int j = 0; j < 13; j++) {
        float2 a = unpack2(Y0[j]); y[0][2 * j] = a.x; y[0][2 * j + 1] = a.y;
        float2 b = unpack2(Y1[j]); y[1][2 * j] = b.x; y[1][2 * j + 1] = b.y;
        float2 d = unpack2(Y2[j]); y[2][2 * j] = d.x; y[2][2 * j + 1] = d.y;
    }
    __syncthreads();   // Ss ready

    // ---- z[w] = sum_k sum_v y[k][v] * As[k][v][w] ----------------------------
    ull zacc[14];
    #pragma unroll
    for (int j = 0; j < 14; j++) zacc[j] = 0ull;
    #pragma unroll
    for (int k = 0; k < KK; k++) {
        for (int v = 0; v < VV; v++) {
            ull yy = pack2(y[k][v], y[k][v]);
            const ull* ar = reinterpret_cast<const ull*>(&As[(k * VV + v) * 28]);
            #pragma unroll
            for (int j = 0; j < 14; j++) zacc[j] = fma2(yy, ar[j], zacc[j]);
        }
    }
    float z[VV + 3];
    #pragma unroll
    for (int j = 0; j < 14; j++) {
        float2 a = unpack2(zacc[j]);
        z[2 * j] = a.x;
        if (2 * j + 1 < VV + 3) z[2 * j + 1] = a.y;
    }
    float b0 = bgl[c], b1 = bgl[CC + c], b2 = bgl[2 * CC + c];
    float s = 0.f, s2 = 0.f;
    #pragma unroll
    for (int w = 0; w < VV; w++) {
        z[w] += b0 * Ss[w] + b1 * Ss[VV + w] + b2 * Ss[2 * VV + w];
        s += z[w]; s2 += z[w] * z[w];
    }
    float2 st = ln_stats(s, s2, red, 1.f / (float)FRA);
    #pragma unroll
    for (int w = 0; w < VV; w++) {
        float u = (z[w] - st.x) * st.y * lw1[c * VV + w] + lb1[c * VV + w];
        g_U[c * TP * VV + (t + 8) * VV + w] = fmaxf(u, 0.f);
    }
}

// ------------- causal temporal conv, 4-way channel split -> partials ----------
// grid (32 t, 4 o, 4 c-split), 128 threads; 4 internal chunks of 16 channels.
__global__ void __launch_bounds__(128) k_tconv(const float* __restrict__ Wtl) {
    __shared__ __align__(16) ull Us2[8][12][26];   // c-pairs x t-span x v(pad26)
    __shared__ __align__(16) ull Ws2[8][GG][64];   // c-pairs x g x o
    float* Usf = reinterpret_cast<float*>(Us2);
    float* Wsf = reinterpret_cast<float*>(Ws2);
    int t0 = blockIdx.x * 4;
    int o0 = blockIdx.y * 64;
    int tid = threadIdx.x;
    int lane = tid & 31, tw = tid >> 5;

    ull accA[26], accB[26];
    #pragma unroll
    for (int i = 0; i < 26; i++) { accA[i] = 0ull; accB[i] = 0ull; }

    for (int ch = 0; ch < 4; ch++) {
        int cb = blockIdx.z * 64 + ch * 16;
        for (int i = tid; i < 16 * 12 * VV; i += 128) {
            int cl = i / (12 * VV), r = i - cl * (12 * VV);
            int trow = r / VV, v = r - trow * VV;
            Usf[((((cl >> 1) * 12 + trow) * 26) + v) * 2 + (cl & 1)] =
                g_U[(cb + cl) * TP * VV + t0 * VV + r];
        }
        for (int i = tid; i < 8 * 12; i += 128) Us2[i / 12][i % 12][25] = 0ull;
        for (int i = tid; i < 64 * 16 * GG; i += 128) {
            int ol = i / (16 * GG), r = i - ol * (16 * GG);
            int cl = r / GG, g = r - cl * GG;
            Wsf[((((cl >> 1) * GG + g) * 64) + ol) * 2 + (cl & 1)] =
                Wtl[(o0 + ol) * (CC * GG) + (cb + cl) * GG + g];
        }
        __syncthreads();
        #pragma unroll 2
        for (int c2 = 0; c2 < 8; c2++) {
            #pragma unroll
            for (int g = 0; g < GG; g++) {
                ull wa = Ws2[c2][g][lane];
                ull wb = Ws2[c2][g][lane + 32];
                const ulonglong2* up =
                    reinterpret_cast<const ulonglong2*>(&Us2[c2][tw + 8 - g][0]);
                #pragma unroll
                for (int j = 0; j < 13; j++) {
                    ulonglong2 u = up[j];
                    accA[2 * j]     = fma2(wa, u.x, accA[2 * j]);
                    accA[2 * j + 1] = fma2(wa, u.y, accA[2 * j + 1]);
                    accB[2 * j]     = fma2(wb, u.x, accB[2 * j]);
                    accB[2 * j + 1] = fma2(wb, u.y, accB[2 * j + 1]);
                }
            }
        }
        __syncthreads();
    }
    int t = t0 + tw;
    float* dstA = &g_P[blockIdx.z][(t * CC + o0 + lane) * PSTR];
    float* dstB = &g_P[blockIdx.z][(t * CC + o0 + lane + 32) * PSTR];
    float va[26], vb[26];
    #pragma unroll
    for (int v = 0; v < 26; v++) {
        float2 a = unpack2(accA[v]); va[v] = a.x + a.y;
        float2 b = unpack2(accB[v]); vb[v] = b.x + b.y;
    }
    #pragma unroll
    for (int j = 0; j < 6; j++) {
        reinterpret_cast<float4*>(dstA)[j] =
            make_float4(va[4 * j], va[4 * j + 1], va[4 * j + 2], va[4 * j + 3]);
        reinterpret_cast<float4*>(dstB)[j] =
            make_float4(vb[4 * j], vb[4 * j + 1], vb[4 * j + 2], vb[4 * j + 3]);
    }
    dstA[24] = va[24];
    dstB[24] = vb[24];
}

// ------- final: reduce partials + LN2 + residual + ReLU + pool + classify -----
__global__ void __launch_bounds__(256) k_out(
    const float* __restrict__ btp, const float* __restrict__ lw2,
    const float* __restrict__ lb2, const float* __restrict__ Wout,
    const float* __restrict__ bout, float* __restrict__ out) {
    int t = blockIdx.x, c = threadIdx.x;
    __shared__ float red[18];
    __shared__ float pooled[CC];
    float z[VV];
    float btv = btp[c];
    #pragma unroll
    for (int w = 0; w < VV; w++) z[w] = btv;
    #pragma unroll
    for (int p = 0; p < NPART; p++) {
        const float* src = &g_P[p][(t * CC + c) * PSTR];
        #pragma unroll
        for (int j = 0; j < 6; j++) {
            float4 f = reinterpret_cast<const float4*>(src)[j];
            z[4 * j] += f.x; z[4 * j + 1] += f.y;
            z[4 * j + 2] += f.z; z[4 * j + 3] += f.w;
        }
        z[24] += src[24];
    }
    float s = 0.f, s2 = 0.f;
    #pragma unroll
    for (int w = 0; w < VV; w++) { s += z[w]; s2 += z[w] * z[w]; }
    float2 st = ln_stats(s, s2, red, 1.f / (float)FRA);
    const float* Hi = g_H[0];   // layer-8 input
    float acc = 0.f;
    #pragma unroll
    for (int w = 0; w < VV; w++) {
        float val = (z[w] - st.x) * st.y * lw2[c * VV + w] + lb2[c * VV + w];
        float res = (t >= 4) ? Hi[(t - 4) * FRA + c * VV + w] : 0.f;
        acc += fmaxf(val + res, 0.f);
    }
    pooled[c] = acc * (1.f / (float)VV);
    __syncthreads();
    if (c < NCC) {
        float a = bout[c];
        for (int q = 0; q < CC; q++) a = fmaf(Wout[c * CC + q], pooled[q], a);
        out[t * NCC + c] = a;
    }
}

// ------------------------------- launcher -------------------------------------
extern "C" void kernel_launch(void* const* d_in, const int* in_sizes, int n_in,
                              void* d_out, int out_size) {
    const float* x    = (const float*)d_in[0];
    const float* Aadj = (const float*)d_in[1];
    const float* lniw = (const float*)d_in[2];
    const float* lnib = (const float*)d_in[3];
    const float* Win  = (const float*)d_in[4];
    const float* bin  = (const float*)d_in[5];
    const float* Wg   = (const float*)d_in[6];
    const float* bg   = (const float*)d_in[7];
    const float* ln1w = (const float*)d_in[8];
    const float* ln1b = (const float*)d_in[9];
    const float* Wt   = (const float*)d_in[10];
    const float* bt   = (const float*)d_in[11];
    const float* ln2w = (const float*)d_in[12];
    const float* ln2b = (const float*)d_in[13];
    const float* imp  = (const float*)d_in[14];
    const float* Wout = (const float*)d_in[15];
    const float* bout = (const float*)d_in[16];
    float* out = (float*)d_out;

    k_wgt<<<dim3(24, 8, LL), dim3(32, 8)>>>(Wg);
    k_input<<<TT, 256>>>(x, lniw, lnib, Win, bin);
    for (int l = 0; l < LL; l++) {
        int p = (l > 0) ? (l - 1) : 0;
        k_gcn<<<TT + 1, 256>>>(l, bg + l * KC, Aadj, imp + l * KK * VV * VV,
                               ln1w + l * CC * VV, ln1b + l * CC * VV,
                               bt + p * CC, ln2w + p * CC * VV, ln2b + p * CC * VV);
        k_tconv<<<dim3(32, 4, NPART), 128>>>(Wt + (size_t)l * CC * CC * GG);
    }
    k_out<<<TT, 256>>>(bt + 8 * CC, ln2w + 8 * CC * VV, ln2b + 8 * CC * VV,
                       Wout, bout, out);
}